// round 11
// baseline (speedup 1.0000x reference)
#include <cuda_runtime.h>
#include <cuda_bf16.h>
#include <math.h>
#include <stdint.h>

// Problem constants
#define BB 4
#define MM 2048
#define DD 1024
#define HH 16
#define DH 64
#define RR 256
#define FD 2048
#define RR1 512
#define RR2 512
#define NN (BB*MM)   // 8192 tokens

typedef __nv_bfloat16 bf16;
typedef __nv_bfloat162 bf162;

// ---------------------------------------------------------------------------
// Scratch (device globals; allocation-free)
// ---------------------------------------------------------------------------
__device__ bf16 g_bXN  [NN*DD];
__device__ bf16 g_bPqkv[NN*3*RR];     // packed [N, 768]: Pq|Pk|Pv
__device__ bf16 g_bQ   [NN*DD];
__device__ bf16 g_bK   [NN*DD];
__device__ bf16 g_bV   [NN*DD];
__device__ bf16 g_bAO  [NN*DD];
__device__ bf16 g_bXN2 [NN*DD];
__device__ bf16 g_bP2  [NN*RR1];
__device__ bf16 g_bG   [NN*FD];
__device__ bf16 g_bT   [NN*RR2];
// bf16 weights ([K, N] row-major, as consumed by hgemm's B path)
__device__ bf16 g_wUqkv[DD*3*RR];     // packed [1024, 768]: Uq|Uk|Uv
__device__ bf16 g_wVq [RR*DD];
__device__ bf16 g_wVk [RR*DD];
__device__ bf16 g_wVv [RR*DD];
__device__ bf16 g_wWoT[DD*DD];
__device__ bf16 g_wU1 [DD*RR1];
__device__ bf16 g_wV1P[RR1*2*FD];     // V1 with columns permuted for GEGLU fusion
__device__ bf16 g_wU2 [FD*RR2];
__device__ bf16 g_wV2 [RR2*DD];
// fp32 rope tables
__device__ float g_ropeC[MM*32];
__device__ float g_ropeS[MM*32];

// ---------------------------------------------------------------------------
// Small PTX helpers
// ---------------------------------------------------------------------------
__device__ __forceinline__ void cp16(uint32_t dst, const void* src) {
    asm volatile("cp.async.cg.shared.global [%0], [%1], 16;\n" :: "r"(dst), "l"(src));
}
__device__ __forceinline__ void cp_commit() {
    asm volatile("cp.async.commit_group;\n" ::: "memory");
}
__device__ __forceinline__ void ldsm4(uint32_t* r, uint32_t addr) {
    asm volatile("ldmatrix.sync.aligned.m8n8.x4.shared.b16 {%0,%1,%2,%3}, [%4];\n"
        : "=r"(r[0]), "=r"(r[1]), "=r"(r[2]), "=r"(r[3]) : "r"(addr));
}
__device__ __forceinline__ void ldsm4t(uint32_t* r, uint32_t addr) {
    asm volatile("ldmatrix.sync.aligned.m8n8.x4.trans.shared.b16 {%0,%1,%2,%3}, [%4];\n"
        : "=r"(r[0]), "=r"(r[1]), "=r"(r[2]), "=r"(r[3]) : "r"(addr));
}
__device__ __forceinline__ void mma_bf16(float* c, const uint32_t* a, uint32_t b0, uint32_t b1) {
    asm volatile(
        "mma.sync.aligned.m16n8k16.row.col.f32.bf16.bf16.f32 "
        "{%0,%1,%2,%3}, {%4,%5,%6,%7}, {%8,%9}, {%0,%1,%2,%3};\n"
        : "+f"(c[0]), "+f"(c[1]), "+f"(c[2]), "+f"(c[3])
        : "r"(a[0]), "r"(a[1]), "r"(a[2]), "r"(a[3]), "r"(b0), "r"(b1));
}
__device__ __forceinline__ uint32_t packbf(float a, float b) {
    bf162 t = __floats2bfloat162_rn(a, b);
    return *reinterpret_cast<uint32_t*>(&t);
}

__device__ __forceinline__ float gelu_t(float x) {
    float x3 = x*x*x;
    return 0.5f * x * (1.f + tanhf(0.7978845608028654f * (x + 0.044715f*x3)));
}

// ---------------------------------------------------------------------------
// 3-stage pipelined bf16 GEMM core. Smem ring: stage s -> A at s*16KB,
// B at 48KB + s*16KB (total 96KB). One __syncthreads per k-iter.
// Requires KT >= 2 (all shapes here have KT >= 4).
// ---------------------------------------------------------------------------
#define HG_SMEM 98304

#define HG_MAIN_LOOP3                                                         \
    issue(0, 0);                                                              \
    cp_commit();                                                              \
    issue(1, 1);                                                              \
    cp_commit();                                                              \
    for (int kt = 0; kt < KT; kt++) {                                         \
        if (kt + 1 < KT)                                                      \
            asm volatile("cp.async.wait_group 1;\n" ::: "memory");            \
        else                                                                  \
            asm volatile("cp.async.wait_group 0;\n" ::: "memory");            \
        __syncthreads();                                                      \
        if (kt + 2 < KT) {                                                    \
            int nb = (kt + 2) % 3;                                            \
            issue(kt + 2, nb);                                                \
            cp_commit();                                                      \
        }                                                                     \
        const int buf = kt % 3;                                               \
        const uint32_t aBase = sA + buf * 16384;                              \
        const uint32_t bBase = sB + buf * 16384;                              \
        _Pragma("unroll")                                                     \
        for (int ks = 0; ks < 4; ks++) {                                      \
            uint32_t afr[2][4];                                               \
            _Pragma("unroll")                                                 \
            for (int mt = 0; mt < 2; mt++) {                                  \
                int row = wm + mt * 16 + (lane & 15);                         \
                int ch = 2 * ks + (lane >> 4);                                \
                ldsm4(afr[mt], aBase + (((row << 6) + ((ch ^ (row & 7)) << 3)) << 1)); \
            }                                                                 \
            uint32_t bfr[4][4];                                               \
            _Pragma("unroll")                                                 \
            for (int nt = 0; nt < 4; nt++) {                                  \
                int k = ks * 16 + (lane & 15);                                \
                int ch = (wn >> 3) + nt * 2 + (lane >> 4);                    \
                int swc = (ch & 8) | ((ch & 7) ^ (k & 7));                    \
                ldsm4t(bfr[nt], bBase + (((k << 7) + (swc << 3)) << 1));      \
            }                                                                 \
            _Pragma("unroll")                                                 \
            for (int mt = 0; mt < 2; mt++)                                    \
                _Pragma("unroll")                                             \
                for (int nt = 0; nt < 4; nt++) {                              \
                    mma_bf16(acc[mt][nt*2+0], afr[mt], bfr[nt][0], bfr[nt][1]); \
                    mma_bf16(acc[mt][nt*2+1], afr[mt], bfr[nt][2], bfr[nt][3]); \
                }                                                             \
        }                                                                     \
    }

#define HG_ISSUE_LAMBDA(Aexpr, ldaexpr, Bexpr, Ncexpr)                        \
    auto issue = [&](int kt, int b) {                                         \
        const int k0 = kt << 6;                                               \
        const uint32_t da = sA + b * 16384;                                   \
        _Pragma("unroll")                                                     \
        for (int t = 0; t < 4; t++) {                                         \
            int j = tid + (t << 8);                                           \
            int r = j >> 3, c = j & 7;                                        \
            cp16(da + (((r << 6) + ((c ^ (r & 7)) << 3)) << 1),               \
                 (Aexpr) + (size_t)(m0 + r) * (ldaexpr) + k0 + (c << 3));     \
        }                                                                     \
        const uint32_t db = sB + b * 16384;                                   \
        _Pragma("unroll")                                                     \
        for (int t = 0; t < 4; t++) {                                         \
            int j = tid + (t << 8);                                           \
            int r = j >> 4, c = j & 15;                                       \
            int swc = (c & 8) | ((c & 7) ^ (r & 7));                          \
            cp16(db + (((r << 7) + (swc << 3)) << 1),                         \
                 (Bexpr) + (size_t)(k0 + r) * (Ncexpr) + n0 + (c << 3));      \
        }                                                                     \
    };

template<bool BIAS, bool RES, bool F32OUT>
__global__ __launch_bounds__(256, 2) void hgemm(
    const bf16* __restrict__ A, const bf16* __restrict__ B,
    const float* __restrict__ bias, const float* __restrict__ res,
    void* __restrict__ Cout, int Nc, int Kd, int lda)
{
    extern __shared__ char smraw[];
    const int tid = threadIdx.x, lane = tid & 31, wid = tid >> 5;
    const int wm = (wid & 3) << 5;
    const int wn = (wid >> 2) << 6;
    const int m0 = blockIdx.y << 7, n0 = blockIdx.x << 7;
    const int KT = Kd >> 6;
    const uint32_t sA = (uint32_t)__cvta_generic_to_shared(smraw);
    const uint32_t sB = sA + 49152;

    float acc[2][8][4];
    #pragma unroll
    for (int i = 0; i < 2; i++)
        #pragma unroll
        for (int j = 0; j < 8; j++)
            #pragma unroll
            for (int k = 0; k < 4; k++) acc[i][j][k] = 0.f;

    HG_ISSUE_LAMBDA(A, lda, B, Nc)
    HG_MAIN_LOOP3

    const int g = lane >> 2, q = (lane & 3) << 1;
    #pragma unroll
    for (int mt = 0; mt < 2; mt++)
        #pragma unroll
        for (int n8 = 0; n8 < 8; n8++) {
            int n = n0 + wn + n8 * 8 + q;
            float b0 = 0.f, b1 = 0.f;
            if (BIAS) { b0 = bias[n]; b1 = bias[n + 1]; }
            #pragma unroll
            for (int hh = 0; hh < 2; hh++) {
                int m = m0 + wm + mt * 16 + g + hh * 8;
                float v0 = acc[mt][n8][hh*2+0] + b0;
                float v1 = acc[mt][n8][hh*2+1] + b1;
                size_t off = (size_t)m * Nc + n;
                if (RES) {
                    const float* rp = res + off;
                    v0 += rp[0]; v1 += rp[1];
                }
                if (F32OUT) {
                    float* C = (float*)Cout;
                    C[off] = v0; C[off + 1] = v1;
                } else {
                    bf162* C = (bf162*)Cout;
                    C[off >> 1] = __floats2bfloat162_rn(v0, v1);
                }
            }
        }
}

// ---------------------------------------------------------------------------
// Merged Q/K/V expand: grid.z selects (B, bias, C); A = Pqkv + z*RR, lda=768.
// Nc = 1024, Kd = 256 for all three.
// ---------------------------------------------------------------------------
struct Expand3 {
    const bf16* B[3];
    const float* bias[3];
    bf16* C[3];
    const bf16* A;       // bPqkv
};

__global__ __launch_bounds__(256, 2) void hgemm_expand3(Expand3 ex)
{
    extern __shared__ char smraw[];
    const int tid = threadIdx.x, lane = tid & 31, wid = tid >> 5;
    const int wm = (wid & 3) << 5;
    const int wn = (wid >> 2) << 6;
    const int m0 = blockIdx.y << 7, n0 = blockIdx.x << 7;
    const int z = blockIdx.z;
    const int KT = RR >> 6;                 // 4
    const uint32_t sA = (uint32_t)__cvta_generic_to_shared(smraw);
    const uint32_t sB = sA + 49152;

    const bf16* A = ex.A + z * RR;
    const bf16* B = ex.B[z];
    const float* bias = ex.bias[z];
    bf16* Cb = ex.C[z];

    float acc[2][8][4];
    #pragma unroll
    for (int i = 0; i < 2; i++)
        #pragma unroll
        for (int j = 0; j < 8; j++)
            #pragma unroll
            for (int k = 0; k < 4; k++) acc[i][j][k] = 0.f;

    HG_ISSUE_LAMBDA(A, 3*RR, B, DD)
    HG_MAIN_LOOP3

    const int g = lane >> 2, q = (lane & 3) << 1;
    #pragma unroll
    for (int mt = 0; mt < 2; mt++)
        #pragma unroll
        for (int n8 = 0; n8 < 8; n8++) {
            int n = n0 + wn + n8 * 8 + q;
            float b0 = bias[n], b1 = bias[n + 1];
            #pragma unroll
            for (int hh = 0; hh < 2; hh++) {
                int m = m0 + wm + mt * 16 + g + hh * 8;
                float v0 = acc[mt][n8][hh*2+0] + b0;
                float v1 = acc[mt][n8][hh*2+1] + b1;
                size_t off = (size_t)m * DD + n;
                ((bf162*)Cb)[off >> 1] = __floats2bfloat162_rn(v0, v1);
            }
        }
}

// ---------------------------------------------------------------------------
// GEGLU-fused GEMM for the V1 expand (columns permuted at 32-granularity).
// ---------------------------------------------------------------------------
__global__ __launch_bounds__(256, 2) void hgemm_geglu(
    const bf16* __restrict__ A, const bf16* __restrict__ B,
    const float* __restrict__ bias,         // b1, original index space [2*FD]
    bf16* __restrict__ G, int Nc, int Kd, int lda)
{
    extern __shared__ char smraw[];
    const int tid = threadIdx.x, lane = tid & 31, wid = tid >> 5;
    const int wm = (wid & 3) << 5;
    const int wn = (wid >> 2) << 6;
    const int m0 = blockIdx.y << 7, n0 = blockIdx.x << 7;
    const int KT = Kd >> 6;
    const uint32_t sA = (uint32_t)__cvta_generic_to_shared(smraw);
    const uint32_t sB = sA + 49152;

    float acc[2][8][4];
    #pragma unroll
    for (int i = 0; i < 2; i++)
        #pragma unroll
        for (int j = 0; j < 8; j++)
            #pragma unroll
            for (int k = 0; k < 4; k++) acc[i][j][k] = 0.f;

    HG_ISSUE_LAMBDA(A, lda, B, Nc)
    HG_MAIN_LOOP3

    const int g = lane >> 2, q = (lane & 3) << 1;
    const int t32 = (n0 + wn) >> 6;             // which 64-block
    const float* b1a = bias + t32 * 32;         // h1 biases
    const float* b1b = bias + FD + t32 * 32;    // h2 biases
    #pragma unroll
    for (int n8 = 0; n8 < 4; n8++) {
        int j = n8 * 8 + q;                     // local gate index 0..31
        float ba0 = b1a[j],     ba1 = b1a[j + 1];
        float bb0 = b1b[j],     bb1 = b1b[j + 1];
        int gc = t32 * 32 + j;                  // global gate column
        #pragma unroll
        for (int mt = 0; mt < 2; mt++)
            #pragma unroll
            for (int hh = 0; hh < 2; hh++) {
                int m = m0 + wm + mt * 16 + g + hh * 8;
                float h10 = acc[mt][n8][hh*2+0] + ba0;
                float h11 = acc[mt][n8][hh*2+1] + ba1;
                float h20 = acc[mt][n8+4][hh*2+0] + bb0;
                float h21 = acc[mt][n8+4][hh*2+1] + bb1;
                *(bf162*)&G[(size_t)m * FD + gc] =
                    __floats2bfloat162_rn(gelu_t(h10)*h20, gelu_t(h11)*h21);
            }
    }
}

// ---------------------------------------------------------------------------
// Weight conversions
// ---------------------------------------------------------------------------
__global__ __launch_bounds__(256) void f2b_kernel(
    const float* __restrict__ s, bf16* __restrict__ d)
{
    int i = blockIdx.x * 256 + threadIdx.x;
    float4 v = ((const float4*)s)[i];
    ((bf162*)d)[i*2+0] = __floats2bfloat162_rn(v.x, v.y);
    ((bf162*)d)[i*2+1] = __floats2bfloat162_rn(v.z, v.w);
}

__global__ __launch_bounds__(256) void f2b_stride_kernel(
    const float* __restrict__ s, bf16* __restrict__ d,
    int srcW, int dstW, int colOff)
{
    int i = blockIdx.x * 256 + threadIdx.x;
    int r = i / (srcW >> 2);
    int c = (i % (srcW >> 2)) << 2;
    float4 v = *(const float4*)&s[(size_t)r * srcW + c];
    bf162* dp = (bf162*)&d[(size_t)r * dstW + colOff + c];
    dp[0] = __floats2bfloat162_rn(v.x, v.y);
    dp[1] = __floats2bfloat162_rn(v.z, v.w);
}

// V1 GEGLU permute-convert
__global__ __launch_bounds__(256) void f2b_geglu_kernel(
    const float* __restrict__ s, bf16* __restrict__ d)
{
    int i = blockIdx.x * 256 + threadIdx.x;   // over RR1 * 2FD / 4
    int r = i >> 10;
    int c = (i & 1023) << 2;
    int t32 = c >> 6, w = c & 63;
    int orig = (w < 32) ? (t32*32 + w) : (FD + t32*32 + (w - 32));
    float4 v = *(const float4*)&s[(size_t)r * (2*FD) + orig];
    bf162* dp = (bf162*)&d[(size_t)r * (2*FD) + c];
    dp[0] = __floats2bfloat162_rn(v.x, v.y);
    dp[1] = __floats2bfloat162_rn(v.z, v.w);
}

__global__ __launch_bounds__(256) void transb_kernel(
    const float* __restrict__ s, bf16* __restrict__ d)
{
    __shared__ float tile[32][33];
    int bx = blockIdx.x * 32;
    int by = blockIdx.y * 32;
    int tx = threadIdx.x & 31, ty = threadIdx.x >> 5;
    #pragma unroll
    for (int i = 0; i < 4; i++) {
        int row = by + ty + i * 8;
        tile[ty + i * 8][tx] = s[(size_t)row * DD + bx + tx];
    }
    __syncthreads();
    #pragma unroll
    for (int i = 0; i < 4; i++) {
        int orow = bx + ty + i * 8;
        d[(size_t)orow * DD + by + tx] = __float2bfloat16(tile[tx][ty + i * 8]);
    }
}

// ---------------------------------------------------------------------------
// LayerNorm
// ---------------------------------------------------------------------------
__device__ __forceinline__ float block_sum(float v) {
    __shared__ float sh[8];
    int lane = threadIdx.x & 31, w = threadIdx.x >> 5;
    #pragma unroll
    for (int o = 16; o; o >>= 1) v += __shfl_xor_sync(0xffffffffu, v, o);
    __syncthreads();
    if (lane == 0) sh[w] = v;
    __syncthreads();
    float t = 0.f;
    #pragma unroll
    for (int i = 0; i < 8; i++) t += sh[i];
    return t;
}

__global__ __launch_bounds__(256) void ln_kernel(
    const float* __restrict__ x, const float* __restrict__ w,
    const float* __restrict__ b, bf16* __restrict__ out)
{
    size_t row = blockIdx.x;
    int t = threadIdx.x;
    float4 v = ((const float4*)(x + row*DD))[t];
    float mu = block_sum(v.x + v.y + v.z + v.w) * (1.f/1024.f);
    float dx = v.x - mu, dy = v.y - mu, dz = v.z - mu, dw = v.w - mu;
    float var = block_sum(dx*dx + dy*dy + dz*dz + dw*dw) * (1.f/1024.f);
    float rs = rsqrtf(var + 1e-5f);
    float4 wv = ((const float4*)w)[t];
    float4 bv = ((const float4*)b)[t];
    bf162* o2 = (bf162*)(out + row*DD);
    o2[t*2+0] = __floats2bfloat162_rn(dx*rs*wv.x + bv.x, dy*rs*wv.y + bv.y);
    o2[t*2+1] = __floats2bfloat162_rn(dz*rs*wv.z + bv.z, dw*rs*wv.w + bv.w);
}

// ---------------------------------------------------------------------------
// RoPE
// ---------------------------------------------------------------------------
__global__ void rope_table_kernel() {
    int idx = blockIdx.x*256 + threadIdx.x;   // 65536 = 2048*32
    int m = idx >> 5, i = idx & 31;
    double e = (double)(2*i) / 64.0;
    float invf = (float)(1.0 / pow(10000.0, e));
    float ang = (float)m * invf;
    double a = (double)ang;
    g_ropeC[idx] = (float)cos(a);
    g_ropeS[idx] = (float)sin(a);
}

__global__ __launch_bounds__(256) void rope_bf16_kernel(
    bf16* __restrict__ Q, bf16* __restrict__ K)
{
    int idx = blockIdx.x*256 + threadIdx.x;   // NN*HH*16 = 2097152
    int n = idx >> 8;
    int r = idx & 255;
    int h = r >> 4;
    int i2 = (r & 15) << 1;
    int m = n & (MM - 1);
    float c0 = g_ropeC[m*32 + i2],     s0 = g_ropeS[m*32 + i2];
    float c1 = g_ropeC[m*32 + i2 + 1], s1 = g_ropeS[m*32 + i2 + 1];
    size_t base = (size_t)n*DD + h*DH;
    bf162* Qp = (bf162*)(Q + base);
    bf162* Kp = (bf162*)(K + base);
    int p = i2 >> 1;
    float2 qa = __bfloat1622float2(Qp[p]);
    float2 qb = __bfloat1622float2(Qp[p + 16]);
    Qp[p]      = __floats2bfloat162_rn(qa.x*c0 - qb.x*s0, qa.y*c1 - qb.y*s1);
    Qp[p + 16] = __floats2bfloat162_rn(qb.x*c0 + qa.x*s0, qb.y*c1 + qa.y*s1);
    float2 ka = __bfloat1622float2(Kp[p]);
    float2 kb = __bfloat1622float2(Kp[p + 16]);
    Kp[p]      = __floats2bfloat162_rn(ka.x*c0 - kb.x*s0, ka.y*c1 - kb.y*s1);
    Kp[p + 16] = __floats2bfloat162_rn(kb.x*c0 + ka.x*s0, kb.y*c1 + ka.y*s1);
}

// ---------------------------------------------------------------------------
// bf16 tensor-core flash attention (proven R7 path).
// ---------------------------------------------------------------------------
#define FAB_SMEM 49664

__global__ __launch_bounds__(256) void fa_bf16_kernel(
    const bf16* __restrict__ Q, const bf16* __restrict__ K,
    const bf16* __restrict__ V, const int* __restrict__ mask,
    bf16* __restrict__ O)
{
    extern __shared__ char fasm[];
    const uint32_t sQ = (uint32_t)__cvta_generic_to_shared(fasm);
    const uint32_t sK = sQ + 16384;
    const uint32_t sV = sQ + 32768;
    float* maskb = (float*)(fasm + 49152);

    const int tid = threadIdx.x, lane = tid & 31, wid = tid >> 5;
    const int m0 = blockIdx.x * 128;
    const int b = blockIdx.y >> 4, h = blockIdx.y & 15;

    {
        const bf16* Qg = Q + ((size_t)(b*MM + m0))*DD + h*DH;
        #pragma unroll
        for (int t = 0; t < 4; t++) {
            int j = tid + (t << 8);
            int r = j >> 3, c = j & 7;
            cp16(sQ + (((r << 6) + ((c ^ (r & 7)) << 3)) << 1),
                 Qg + (size_t)r*DD + (c << 3));
        }
        cp_commit();
    }

    auto issueKV = [&](int tkv, int bb) {
        size_t base = ((size_t)(b*MM + tkv*64))*DD + h*DH;
        #pragma unroll
        for (int t = 0; t < 2; t++) {
            int j = tid + (t << 8);
            int r = j >> 3, c = j & 7;
            uint32_t off = (((r << 6) + ((c ^ (r & 7)) << 3)) << 1) + bb*8192;
            cp16(sK + off, K + base + (size_t)r*DD + (c << 3));
            cp16(sV + off, V + base + (size_t)r*DD + (c << 3));
        }
        if (tid < 64)
            maskb[bb*64 + tid] = mask[b*MM + tkv*64 + tid] ? 0.f : -1e30f;
    };

    issueKV(0, 0);
    cp_commit();
    asm volatile("cp.async.wait_group 0;\n" ::: "memory");
    __syncthreads();

    uint32_t qf[4][4];
    {
        int row = (wid << 4) + (lane & 15);
        #pragma unroll
        for (int ks = 0; ks < 4; ks++) {
            int ch = 2*ks + (lane >> 4);
            ldsm4(qf[ks], sQ + (((row << 6) + ((ch ^ (row & 7)) << 3)) << 1));
        }
    }

    float o_acc[8][4];
    #pragma unroll
    for (int i = 0; i < 8; i++)
        #pragma unroll
        for (int j = 0; j < 4; j++) o_acc[i][j] = 0.f;
    float mrow[2] = {-1e30f, -1e30f}, lrow[2] = {0.f, 0.f};

    int buf = 0;
    for (int t = 0; t < MM/64; t++) {
        if (t + 1 < MM/64) { issueKV(t + 1, buf ^ 1); cp_commit(); }

        float s_acc[8][4];
        #pragma unroll
        for (int i = 0; i < 8; i++)
            #pragma unroll
            for (int j = 0; j < 4; j++) s_acc[i][j] = 0.f;

        const uint32_t kb = sK + buf*8192;
        #pragma unroll
        for (int ks = 0; ks < 4; ks++) {
            #pragma unroll
            for (int kvt = 0; kvt < 4; kvt++) {
                uint32_t kf[4];
                int row = (kvt << 4) + (lane & 15);
                int ch = 2*ks + (lane >> 4);
                ldsm4(kf, kb + (((row << 6) + ((ch ^ (row & 7)) << 3)) << 1));
                mma_bf16(s_acc[kvt*2+0], qf[ks], kf[0], kf[2]);
                mma_bf16(s_acc[kvt*2+1], qf[ks], kf[1], kf[3]);
            }
        }

        const float* mbuf = maskb + buf*64;
        float bias0[8], bias1[8];
        #pragma unroll
        for (int tl = 0; tl < 8; tl++) {
            bias0[tl] = mbuf[tl*8 + ((lane & 3) << 1)];
            bias1[tl] = mbuf[tl*8 + ((lane & 3) << 1) + 1];
        }
        #pragma unroll
        for (int hh = 0; hh < 2; hh++) {
            float mx = -1e30f;
            #pragma unroll
            for (int tl = 0; tl < 8; tl++) {
                float v0 = s_acc[tl][hh*2+0]*0.125f + bias0[tl];
                float v1 = s_acc[tl][hh*2+1]*0.125f + bias1[tl];
                s_acc[tl][hh*2+0] = v0; s_acc[tl][hh*2+1] = v1;
                mx = fmaxf(mx, fmaxf(v0, v1));
            }
            mx = fmaxf(mx, __shfl_xor_sync(0xffffffffu, mx, 1));
            mx = fmaxf(mx, __shfl_xor_sync(0xffffffffu, mx, 2));
            float mn = fmaxf(mrow[hh], mx);
            float corr = __expf(mrow[hh] - mn);
            mrow[hh] = mn;
            float ps = 0.f;
            #pragma unroll
            for (int tl = 0; tl < 8; tl++) {
                float p0 = __expf(s_acc[tl][hh*2+0] - mn);
                float p1 = __expf(s_acc[tl][hh*2+1] - mn);
                s_acc[tl][hh*2+0] = p0; s_acc[tl][hh*2+1] = p1;
                ps += p0 + p1;
            }
            ps += __shfl_xor_sync(0xffffffffu, ps, 1);
            ps += __shfl_xor_sync(0xffffffffu, ps, 2);
            lrow[hh] = lrow[hh]*corr + ps;
            #pragma unroll
            for (int tl = 0; tl < 8; tl++) {
                o_acc[tl][hh*2+0] *= corr;
                o_acc[tl][hh*2+1] *= corr;
            }
        }

        uint32_t ap[4][4];
        #pragma unroll
        for (int j = 0; j < 4; j++) {
            ap[j][0] = packbf(s_acc[2*j][0],   s_acc[2*j][1]);
            ap[j][1] = packbf(s_acc[2*j][2],   s_acc[2*j][3]);
            ap[j][2] = packbf(s_acc[2*j+1][0], s_acc[2*j+1][1]);
            ap[j][3] = packbf(s_acc[2*j+1][2], s_acc[2*j+1][3]);
        }

        const uint32_t vb = sV + buf*8192;
        #pragma unroll
        for (int j = 0; j < 4; j++) {
            #pragma unroll
            for (int nt = 0; nt < 4; nt++) {
                uint32_t vf[4];
                int krow = (j << 4) + (lane & 15);
                int ch = nt*2 + (lane >> 4);
                ldsm4t(vf, vb + (((krow << 6) + ((ch ^ (krow & 7)) << 3)) << 1));
                mma_bf16(o_acc[nt*2+0], ap[j], vf[0], vf[1]);
                mma_bf16(o_acc[nt*2+1], ap[j], vf[2], vf[3]);
            }
        }

        asm volatile("cp.async.wait_group 0;\n" ::: "memory");
        __syncthreads();
        buf ^= 1;
    }

    #pragma unroll
    for (int hh = 0; hh < 2; hh++) {
        float inv = 1.f / lrow[hh];
        int token = b*MM + m0 + (wid << 4) + (lane >> 2) + hh*8;
        size_t rowoff = (size_t)token*DD + h*DH + ((lane & 3) << 1);
        #pragma unroll
        for (int tl = 0; tl < 8; tl++) {
            *(bf162*)&O[rowoff + tl*8] =
                __floats2bfloat162_rn(o_acc[tl][hh*2+0]*inv, o_acc[tl][hh*2+1]*inv);
        }
    }
}

// ---------------------------------------------------------------------------
// Host launcher
// ---------------------------------------------------------------------------
extern "C" void kernel_launch(void* const* d_in, const int* in_sizes, int n_in,
                              void* d_out, int out_size)
{
    const float* x    = (const float*)d_in[0];
    const int*   mask = (const int*)  d_in[1];
    const float* ln1w = (const float*)d_in[2];
    const float* ln1b = (const float*)d_in[3];
    const float* ln2w = (const float*)d_in[4];
    const float* ln2b = (const float*)d_in[5];
    const float* Uq   = (const float*)d_in[6];
    const float* Uk   = (const float*)d_in[7];
    const float* Uv   = (const float*)d_in[8];
    const float* Vq   = (const float*)d_in[9];
    const float* Vk   = (const float*)d_in[10];
    const float* Vv   = (const float*)d_in[11];
    const float* bq   = (const float*)d_in[12];
    const float* bk   = (const float*)d_in[13];
    const float* bv   = (const float*)d_in[14];
    const float* Wo   = (const float*)d_in[15];
    const float* Wob  = (const float*)d_in[16];
    const float* U1   = (const float*)d_in[17];
    const float* V1   = (const float*)d_in[18];
    const float* b1   = (const float*)d_in[19];
    const float* U2   = (const float*)d_in[20];
    const float* V2   = (const float*)d_in[21];
    const float* b2   = (const float*)d_in[22];
    float* out = (float*)d_out;

    void* p;
    #define SYMB(var, sym) cudaGetSymbolAddress(&p, sym); bf16* var = (bf16*)p;
    SYMB(bXN,  g_bXN);   SYMB(bPqkv, g_bPqkv);
    SYMB(bQ,   g_bQ);    SYMB(bK,  g_bK);   SYMB(bV,  g_bV);
    SYMB(bAO,  g_bAO);   SYMB(bXN2,g_bXN2); SYMB(bP2, g_bP2);
    SYMB(bG,   g_bG);    SYMB(bT,  g_bT);
    SYMB(wUqkv,g_wUqkv);
    SYMB(wVq,  g_wVq);   SYMB(wVk, g_wVk);  SYMB(wVv, g_wVv);
    SYMB(wWoT, g_wWoT);  SYMB(wU1, g_wU1);  SYMB(wV1P,g_wV1P);
    SYMB(wU2,  g_wU2);   SYMB(wV2, g_wV2);
    #undef SYMB

    cudaFuncSetAttribute(fa_bf16_kernel,
        cudaFuncAttributeMaxDynamicSharedMemorySize, FAB_SMEM);
    cudaFuncSetAttribute(hgemm<false,false,false>,
        cudaFuncAttributeMaxDynamicSharedMemorySize, HG_SMEM);
    cudaFuncSetAttribute(hgemm<true,false,false>,
        cudaFuncAttributeMaxDynamicSharedMemorySize, HG_SMEM);
    cudaFuncSetAttribute(hgemm<true,true,true>,
        cudaFuncAttributeMaxDynamicSharedMemorySize, HG_SMEM);
    cudaFuncSetAttribute(hgemm_geglu,
        cudaFuncAttributeMaxDynamicSharedMemorySize, HG_SMEM);
    cudaFuncSetAttribute(hgemm_expand3,
        cudaFuncAttributeMaxDynamicSharedMemorySize, HG_SMEM);

    // LN1
    ln_kernel<<<NN, 256>>>(x, ln1w, ln1b, bXN);
    // pack Uq|Uk|Uv -> [1024, 768]
    f2b_stride_kernel<<<(DD*RR/4)/256, 256>>>(Uq, wUqkv, RR, 3*RR, 0);
    f2b_stride_kernel<<<(DD*RR/4)/256, 256>>>(Uk, wUqkv, RR, 3*RR, RR);
    f2b_stride_kernel<<<(DD*RR/4)/256, 256>>>(Uv, wUqkv, RR, 3*RR, 2*RR);
    rope_table_kernel<<<256, 256>>>();
    // merged rank projection
    hgemm<false,false,false><<<dim3(3*RR/128, NN/128), 256, HG_SMEM>>>(
        bXN, wUqkv, nullptr, nullptr, bPqkv, 3*RR, DD, DD);

    // Remaining weight conversions
    #define CVT(src, dst, n) f2b_kernel<<<(n)/1024, 256>>>(src, dst)
    CVT(Vq, wVq, RR*DD);  CVT(Vk, wVk, RR*DD);  CVT(Vv, wVv, RR*DD);
    CVT(U1, wU1, DD*RR1); CVT(U2, wU2, FD*RR2); CVT(V2, wV2, RR2*DD);
    #undef CVT
    f2b_geglu_kernel<<<(RR1*2*FD/4)/256, 256>>>(V1, wV1P);
    transb_kernel<<<dim3(32,32), 256>>>(Wo, wWoT);

    // Merged expand: z in {Q,K,V}
    {
        Expand3 ex;
        ex.B[0] = wVq;  ex.B[1] = wVk;  ex.B[2] = wVv;
        ex.bias[0] = bq; ex.bias[1] = bk; ex.bias[2] = bv;
        ex.C[0] = bQ;   ex.C[1] = bK;   ex.C[2] = bV;
        ex.A = bPqkv;
        hgemm_expand3<<<dim3(DD/128, NN/128, 3), 256, HG_SMEM>>>(ex);
    }

    // RoPE in place on bf16 Q, K
    rope_bf16_kernel<<<(NN*HH*16)/256, 256>>>(bQ, bK);

    // bf16 flash attention -> bAO
    fa_bf16_kernel<<<dim3(MM/128, BB*HH), 256, FAB_SMEM>>>(bQ, bK, bV, mask, bAO);

    // Out-proj + bias + residual(x) -> d_out fp32
    hgemm<true,true,true><<<dim3(DD/128, NN/128), 256, HG_SMEM>>>(
        bAO, wWoT, Wob, x, out, DD, DD, DD);

    // LN2
    ln_kernel<<<NN, 256>>>(out, ln2w, ln2b, bXN2);

    // FFN rank path: P2 = XN2 @ U1 ; G = geglu(P2 @ V1P + b1) fused ; T = G @ U2
    hgemm<false,false,false><<<dim3(RR1/128, NN/128), 256, HG_SMEM>>>(
        bXN2, wU1, nullptr, nullptr, bP2, RR1, DD, DD);
    hgemm_geglu<<<dim3((2*FD)/128, NN/128), 256, HG_SMEM>>>(
        bP2, wV1P, b1, bG, 2*FD, RR1, RR1);
    hgemm<false,false,false><<<dim3(RR2/128, NN/128), 256, HG_SMEM>>>(
        bG, wU2, nullptr, nullptr, bT, RR2, FD, FD);

    // Final: out = out(residual) + T @ V2 + b2 (in-place residual safe)
    hgemm<true,true,true><<<dim3(DD/128, NN/128), 256, HG_SMEM>>>(
        bT, wV2, b2, out, out, DD, RR2, RR2);
}